// round 2
// baseline (speedup 1.0000x reference)
#include <cuda_runtime.h>
#include <cstdint>

#define S_LEN 256
#define BATCH 64
#define HID   1024
#define G4    4096
#define MTOT  (S_LEN*BATCH)
#define RGRID 128

// ---------------- device scratch (static: no runtime allocation allowed) ----
__device__ float    g_xz[(size_t)S_LEN * G4 * BATCH];   // 256 MB, layout [s][n][b]
__device__ unsigned g_hbuf[2][BATCH*HID];               // ping-pong h (tf32 bits)
__device__ unsigned g_bar;                              // monotonic grid barrier

// ---------------- helpers ----------------------------------------------------
__device__ __forceinline__ unsigned f2tf(float x){
  unsigned u; asm("cvt.rna.tf32.f32 %0, %1;" : "=r"(u) : "f"(x)); return u;
}
__device__ __forceinline__ void mma8(float* d, const unsigned* a, unsigned b0, unsigned b1){
  asm volatile("mma.sync.aligned.m16n8k8.row.col.f32.tf32.tf32.f32 "
      "{%0,%1,%2,%3},{%4,%5,%6,%7},{%8,%9},{%0,%1,%2,%3};"
      : "+f"(d[0]),"+f"(d[1]),"+f"(d[2]),"+f"(d[3])
      : "r"(a[0]),"r"(a[1]),"r"(a[2]),"r"(a[3]),"r"(b0),"r"(b1));
}
__device__ __forceinline__ void cp16(void* sm, const void* g){
  unsigned s = (unsigned)__cvta_generic_to_shared(sm);
  asm volatile("cp.async.cg.shared.global [%0], [%1], 16;" :: "r"(s), "l"(g));
}
__device__ __forceinline__ unsigned ld_acq(const unsigned* p){
  unsigned v; asm volatile("ld.acquire.gpu.global.u32 %0, [%1];" : "=r"(v) : "l"(p)); return v;
}

// ---------------- init: reset barrier, h0 -> tf32 ping buffer ----------------
__global__ void init_kernel(const float* __restrict__ h0){
  int i = blockIdx.x*blockDim.x + threadIdx.x;
  if (i == 0) g_bar = 0;
  if (i < BATCH*HID) g_hbuf[0][i] = f2tf(h0[i]);
}

// ---------------- phase 1: xz = x @ Wx^T + b  (tf32 mma GEMM) ----------------
// C[M=16384, N=4096], K=1024. BM=BN=128, BK=32, 8 warps (4m x 2n), warp 32x64.
// Output stored as g_xz[s][n][b] so the recurrent kernel reads coalesced.
__global__ void __launch_bounds__(256,2) gemm_xz_kernel(
    const float* __restrict__ x,
    const float* __restrict__ Wf, const float* __restrict__ Wi,
    const float* __restrict__ Wg, const float* __restrict__ Wo,
    const float* __restrict__ bfp, const float* __restrict__ bip,
    const float* __restrict__ bgp, const float* __restrict__ bop)
{
  __shared__ unsigned a_s[128][36];   // pad 36 -> conflict-free fragment loads
  __shared__ unsigned b_s[128][36];
  const int m0 = blockIdx.y*128, n0 = blockIdx.x*128;
  const int tid = threadIdx.x, wid = tid>>5, lane = tid&31;
  const int wm = wid&3, wn = wid>>2, gid = lane>>2, tig = lane&3;
  // this CTA's 128 N-columns lie inside a single gate block (128 | 1024)
  const int gate = n0 >> 10;
  const float* Wp = (gate==0)?Wf:(gate==1)?Wi:(gate==2)?Wg:Wo;
  const float* bp = (gate==0)?bfp:(gate==1)?bip:(gate==2)?bgp:bop;

  float acc[2][8][4];
  #pragma unroll
  for (int u=0;u<2;u++)
    #pragma unroll
    for (int v=0;v<8;v++)
      #pragma unroll
      for (int w=0;w<4;w++) acc[u][v][w]=0.f;

  const int r = tid>>3, c4 = (tid&7)*4;
  for (int kb=0; kb<HID; kb+=32) {
    #pragma unroll
    for (int rr=r; rr<128; rr+=32) {
      float4 v = *reinterpret_cast<const float4*>(&x[(size_t)(m0+rr)*HID + kb + c4]);
      a_s[rr][c4]=f2tf(v.x); a_s[rr][c4+1]=f2tf(v.y);
      a_s[rr][c4+2]=f2tf(v.z); a_s[rr][c4+3]=f2tf(v.w);
    }
    #pragma unroll
    for (int rr=r; rr<128; rr+=32) {
      int j = (n0 + rr) & 1023;   // row inside this gate's W; Wx = cols [0,H)
      float4 v = *reinterpret_cast<const float4*>(&Wp[(size_t)j*2048 + kb + c4]);
      b_s[rr][c4]=f2tf(v.x); b_s[rr][c4+1]=f2tf(v.y);
      b_s[rr][c4+2]=f2tf(v.z); b_s[rr][c4+3]=f2tf(v.w);
    }
    __syncthreads();
    #pragma unroll
    for (int k8=0;k8<4;k8++){
      unsigned af[2][4], bfr[8][2];
      #pragma unroll
      for (int mt=0;mt<2;mt++){
        int row = wm*32 + mt*16;
        af[mt][0]=a_s[row+gid  ][k8*8+tig];
        af[mt][1]=a_s[row+gid+8][k8*8+tig];
        af[mt][2]=a_s[row+gid  ][k8*8+tig+4];
        af[mt][3]=a_s[row+gid+8][k8*8+tig+4];
      }
      #pragma unroll
      for (int nt=0;nt<8;nt++){
        int col = wn*64 + nt*8 + gid;
        bfr[nt][0]=b_s[col][k8*8+tig];
        bfr[nt][1]=b_s[col][k8*8+tig+4];
      }
      #pragma unroll
      for (int mt=0;mt<2;mt++)
        #pragma unroll
        for (int nt=0;nt<8;nt++)
          mma8(acc[mt][nt], af[mt], bfr[nt][0], bfr[nt][1]);
    }
    __syncthreads();
  }
  // epilogue: add bias, store into [s][n][b] layout
  #pragma unroll
  for (int mt=0;mt<2;mt++){
    #pragma unroll
    for (int nt=0;nt<8;nt++){
      int row0 = m0 + wm*32 + mt*16 + gid;     // global m = s*64 + b
      int col  = n0 + wn*64 + nt*8 + tig*2;    // even
      int j = col & 1023;
      float b0v = bp[j], b1v = bp[j+1];
      int s0 = row0>>6,     bb0 = row0&63;
      int s1 = (row0+8)>>6, bb1 = (row0+8)&63;
      size_t base0 = (size_t)s0*((size_t)G4*BATCH) + (size_t)col*BATCH;
      size_t base1 = (size_t)s1*((size_t)G4*BATCH) + (size_t)col*BATCH;
      g_xz[base0 + bb0]         = acc[mt][nt][0] + b0v;
      g_xz[base0 + BATCH + bb0] = acc[mt][nt][1] + b1v;
      g_xz[base1 + bb1]         = acc[mt][nt][2] + b0v;
      g_xz[base1 + BATCH + bb1] = acc[mt][nt][3] + b1v;
    }
  }
}

// ---------------- phase 2: persistent recurrent kernel -----------------------
// 128 CTAs (1/SM). CTA c owns hidden units j in [8c,8c+8): 32 gate rows of Wh,
// resident in smem (tf32) for all 256 steps. Per step:
//   z(64x32) = xz_slice + h @ Wh^T via tf32 mma, h K-chunks double-buffered via
//   cp.async; gates assembled in-register via shfl_xor(1); grid barrier.
// Local z column c (0..31): gate = c&3, jl = c>>2, global col = gate*1024+j0+jl.
__global__ void __launch_bounds__(256,1) lstm_steps_kernel(
    const float* __restrict__ x, const float* __restrict__ c0,
    const float* __restrict__ Wf,const float* __restrict__ Wi,
    const float* __restrict__ Wg,const float* __restrict__ Wo,
    float* __restrict__ out)
{
  extern __shared__ unsigned smem[];
  unsigned* wh  = smem;                   // 32 x 1028 u32 (pad -> conflict-free)
  unsigned* hs0 = wh  + 32*1028;          // 64 x 132 u32 chunk buffer A
  unsigned* hs1 = hs0 + 64*132;           // 64 x 132 u32 chunk buffer B
  float*    xzs = (float*)(hs1 + 64*132); // 32 x 66 f32 xz slice
  float*    cs  = xzs + 32*66;            // 64 x 8 f32 persistent cell state

  const int tid = threadIdx.x, wid = tid>>5, lane = tid&31;
  const int gid = lane>>2, tig = lane&3;
  const int wm = wid&3, wn = wid>>2;      // 4 m-tiles(16) x 2 n-tiles(16)
  const int cta = blockIdx.x, j0 = cta*8;

  // fill Wh slice: local col c -> Wh row (c&3)*1024 + j0 + (c>>2), K=1024 tf32
  for (int f4 = tid; f4 < 32*256; f4 += 256) {
    int c = f4 >> 8;
    int k = (f4 & 255)*4;
    int gate = c & 3, jl = c >> 2;
    const float* Wp = (gate==0)?Wf:(gate==1)?Wi:(gate==2)?Wg:Wo;
    float4 v = *reinterpret_cast<const float4*>(&Wp[(size_t)(j0+jl)*2048 + 1024 + k]);
    unsigned* dst = &wh[c*1028 + k];
    dst[0]=f2tf(v.x); dst[1]=f2tf(v.y); dst[2]=f2tf(v.z); dst[3]=f2tf(v.w);
  }
  for (int t = tid; t < 512; t += 256) {      // 64 b x 8 jl
    int b = t>>3, jl = t&7;
    cs[t] = c0[b*HID + j0 + jl];
  }
  __syncthreads();

  const size_t HSEQ = (size_t)S_LEN*BATCH*HID;

  for (int s=0; s<S_LEN; s++){
    const unsigned* hr = g_hbuf[s&1];
    unsigned* hwv      = g_hbuf[(s+1)&1];

    // stage this step's xz slice (coalesced; [s][n][b] layout)
    {
      const size_t base = (size_t)s * ((size_t)G4*BATCH);
      #pragma unroll
      for (int it=0; it<8; it++){
        int f = it*256 + tid;
        int c = f>>6, b = f&63;
        int gcol = (c&3)*HID + j0 + (c>>2);
        xzs[c*66 + b] = g_xz[base + (size_t)gcol*BATCH + b];
      }
    }
    // prologue: async-load h chunk 0 (cp.async.cg: L2-coherent)
    #pragma unroll
    for (int it=0; it<8; it++){
      int f4 = it*256 + tid;
      int b = f4>>5, k4 = (f4&31)*4;
      cp16(&hs0[b*132 + k4], &hr[b*HID + k4]);
    }
    asm volatile("cp.async.commit_group;");
    __syncthreads();   // xzs visible

    // init accumulators from xz (bias already included)
    float acc[2][4];
    #pragma unroll
    for (int t2=0;t2<2;t2++){
      int tt = wn*2+t2;
      #pragma unroll
      for (int i=0;i<4;i++){
        int row = wm*16 + gid + ((i>>1)<<3);
        int c = tt*8 + tig*2 + (i&1);
        acc[t2][i] = xzs[c*66 + row];
      }
    }

    #pragma unroll 1
    for (int ch=0; ch<8; ch++){
      unsigned* cur = (ch&1)? hs1 : hs0;
      unsigned* nxt = (ch&1)? hs0 : hs1;
      if (ch < 7){
        #pragma unroll
        for (int it=0; it<8; it++){
          int f4 = it*256 + tid;
          int b = f4>>5, k4 = (f4&31)*4;
          cp16(&nxt[b*132 + k4], &hr[b*HID + (ch+1)*128 + k4]);
        }
        asm volatile("cp.async.commit_group;");
        asm volatile("cp.async.wait_group 1;");
      } else {
        asm volatile("cp.async.wait_group 0;");
      }
      __syncthreads();   // chunk ch fully resident for all warps
      #pragma unroll
      for (int k8=0;k8<16;k8++){
        unsigned af[4];
        int arow = wm*16;
        af[0]=cur[(arow+gid  )*132 + k8*8+tig];
        af[1]=cur[(arow+gid+8)*132 + k8*8+tig];
        af[2]=cur[(arow+gid  )*132 + k8*8+tig+4];
        af[3]=cur[(arow+gid+8)*132 + k8*8+tig+4];
        #pragma unroll
        for (int t2=0;t2<2;t2++){
          int tt = wn*2+t2;
          unsigned b0 = wh[(tt*8+gid)*1028 + ch*128 + k8*8 + tig];
          unsigned b1 = wh[(tt*8+gid)*1028 + ch*128 + k8*8 + tig + 4];
          mma8(acc[t2], af, b0, b1);
        }
      }
      __syncthreads();   // all reads of cur done before it is refilled
    }

    // epilogue: shfl_xor(1) pairs (f,i)<->(g,o); each thread owns one (b,jl)/t2
    #pragma unroll
    for (int t2=0;t2<2;t2++){
      float p0 = __shfl_xor_sync(0xffffffffu, acc[t2][0], 1);
      float p1 = __shfl_xor_sync(0xffffffffu, acc[t2][1], 1);
      float p2 = __shfl_xor_sync(0xffffffffu, acc[t2][2], 1);
      float p3 = __shfl_xor_sync(0xffffffffu, acc[t2][3], 1);
      int tt = wn*2+t2;
      int jl = tt*2 + (tig>>1);
      int b; float zf,zi,zg,zo;
      if ((tig & 1)==0){ b = wm*16+gid;   zf=acc[t2][0]; zi=acc[t2][1]; zg=p0; zo=p1; }
      else             { b = wm*16+gid+8; zf=p2; zi=p3; zg=acc[t2][2]; zo=acc[t2][3]; }
      float fg = 1.f/(1.f+__expf(-zf));
      float ig = 1.f/(1.f+__expf(-zi));
      float gg = tanhf(zg);
      float og = 1.f/(1.f+__expf(-zo));
      float cc = fg*cs[b*8+jl] + ig*gg;
      float hh = og*tanhf(cc);
      cs[b*8+jl] = cc;
      int j = j0 + jl;
      size_t xi = ((size_t)(s*BATCH + b))*HID + j;
      out[xi] = x[xi] + hh;
      __stcg(&hwv[b*HID + j], f2tf(hh));
      if (s == S_LEN-1){
        out[HSEQ + (size_t)b*HID + j]                      = hh;   // h_f
        out[HSEQ + (size_t)BATCH*HID + (size_t)b*HID + j]  = cc;   // c_f
      }
    }

    // grid barrier (monotonic counter; skip after last step)
    if (s < S_LEN-1){
      __syncthreads();
      if (tid == 0){
        __threadfence();
        atomicAdd(&g_bar, 1u);
        unsigned target = (unsigned)RGRID * (unsigned)(s+1);
        while (ld_acq(&g_bar) < target) { }
      }
      __syncthreads();
    }
  }
}

// ---------------- launch ------------------------------------------------------
#define SMEM2_BYTES ((32*1028 + 2*64*132 + 32*66 + 512) * 4)

extern "C" void kernel_launch(void* const* d_in, const int* in_sizes, int n_in,
                              void* d_out, int out_size) {
  const float* x   = (const float*)d_in[0];
  const float* h0  = (const float*)d_in[1];
  const float* c0  = (const float*)d_in[2];
  const float* Wf  = (const float*)d_in[3];
  const float* bf_ = (const float*)d_in[4];
  const float* Wi  = (const float*)d_in[5];
  const float* bi_ = (const float*)d_in[6];
  const float* Wg  = (const float*)d_in[7];
  const float* bg_ = (const float*)d_in[8];
  const float* Wo  = (const float*)d_in[9];
  const float* bo_ = (const float*)d_in[10];
  float* out = (float*)d_out;

  cudaFuncSetAttribute(lstm_steps_kernel,
                       cudaFuncAttributeMaxDynamicSharedMemorySize, SMEM2_BYTES);

  init_kernel<<<256,256>>>(h0);
  gemm_xz_kernel<<<dim3(32,128),256>>>(x, Wf,Wi,Wg,Wo, bf_,bi_,bg_,bo_);
  lstm_steps_kernel<<<RGRID,256,SMEM2_BYTES>>>(x, c0, Wf,Wi,Wg,Wo, out);
}

// round 3
// speedup vs baseline: 1.0417x; 1.0417x over previous
#include <cuda_runtime.h>
#include <cstdint>

#define S_LEN 256
#define BATCH 64
#define HID   1024
#define G4    4096
#define RGRID 128

// ---------------- device scratch (no runtime allocation allowed) ------------
__device__ float    g_xz[(size_t)S_LEN * G4 * BATCH];  // 256 MB, layout [s][n][b]
__device__ unsigned g_hT[2][HID*BATCH];                // h transposed [k=j][b], tf32, SW128-swizzled
__device__ unsigned g_bar;                             // monotonic grid barrier

// ---------------- helpers ----------------------------------------------------
__device__ __forceinline__ unsigned f2tf(float x){
  unsigned u; asm("cvt.rna.tf32.f32 %0, %1;" : "=r"(u) : "f"(x)); return u;
}
__device__ __forceinline__ void mma8(float* d, const unsigned* a, unsigned b0, unsigned b1){
  asm volatile("mma.sync.aligned.m16n8k8.row.col.f32.tf32.tf32.f32 "
      "{%0,%1,%2,%3},{%4,%5,%6,%7},{%8,%9},{%0,%1,%2,%3};"
      : "+f"(d[0]),"+f"(d[1]),"+f"(d[2]),"+f"(d[3])
      : "r"(a[0]),"r"(a[1]),"r"(a[2]),"r"(a[3]),"r"(b0),"r"(b1));
}
__device__ __forceinline__ unsigned ld_acq(const unsigned* p){
  unsigned v; asm volatile("ld.acquire.gpu.global.u32 %0, [%1];" : "=r"(v) : "l"(p)); return v;
}
// swizzled word index inside the [k][b] h buffer (matches SW128 on 4B words)
__device__ __forceinline__ unsigned hswz(unsigned k, unsigned b){
  return k*64u + (b ^ (((k&3u)<<3) | (((b>>5)&1u)<<2)));
}
__device__ __forceinline__ void mbar_init(unsigned mbar, unsigned cnt){
  asm volatile("mbarrier.init.shared.b64 [%0], %1;" :: "r"(mbar), "r"(cnt) : "memory");
}
__device__ __forceinline__ void mbar_expect_tx(unsigned mbar, unsigned bytes){
  asm volatile("mbarrier.arrive.expect_tx.shared.b64 _, [%0], %1;" :: "r"(mbar), "r"(bytes) : "memory");
}
__device__ __forceinline__ void bulk_g2s(unsigned dst, const void* src, unsigned bytes, unsigned mbar){
  asm volatile("cp.async.bulk.shared::cta.global.mbarrier::complete_tx::bytes [%0], [%1], %2, [%3];"
      :: "r"(dst), "l"(src), "r"(bytes), "r"(mbar) : "memory");
}
__device__ __forceinline__ void mbar_wait(unsigned mbar, unsigned parity){
  asm volatile("{\n\t.reg .pred P;\n\t"
    "WL_%=:\n\t"
    "mbarrier.try_wait.parity.acquire.cta.shared::cta.b64 P, [%0], %1, 0x989680;\n\t"
    "@!P bra WL_%=;\n\t}" :: "r"(mbar), "r"(parity) : "memory");
}

// ---------------- phase 1: xz = x @ Wx^T + b  (tf32 mma GEMM) + fused init ---
__global__ void __launch_bounds__(256,2) gemm_xz_kernel(
    const float* __restrict__ x, const float* __restrict__ h0,
    const float* __restrict__ Wf, const float* __restrict__ Wi,
    const float* __restrict__ Wg, const float* __restrict__ Wo,
    const float* __restrict__ bfp, const float* __restrict__ bip,
    const float* __restrict__ bgp, const float* __restrict__ bop)
{
  // fused init: block (0,0) resets barrier and writes h0 (tf32, swizzled [k][b])
  if (blockIdx.x==0 && blockIdx.y==0) {
    if (threadIdx.x==0) g_bar = 0;
    for (int i = threadIdx.x; i < BATCH*HID; i += 256) {
      int b = i >> 10, j = i & 1023;
      g_hT[0][hswz(j, b)] = f2tf(h0[i]);
    }
  }

  __shared__ unsigned a_s[128][36];
  __shared__ unsigned b_s[128][36];
  const int m0 = blockIdx.y*128, n0 = blockIdx.x*128;
  const int tid = threadIdx.x, wid = tid>>5, lane = tid&31;
  const int wm = wid&3, wn = wid>>2, gid = lane>>2, tig = lane&3;
  const int gate = n0 >> 10;
  const float* Wp = (gate==0)?Wf:(gate==1)?Wi:(gate==2)?Wg:Wo;
  const float* bp = (gate==0)?bfp:(gate==1)?bip:(gate==2)?bgp:bop;

  float acc[2][8][4];
  #pragma unroll
  for (int u=0;u<2;u++)
    #pragma unroll
    for (int v=0;v<8;v++)
      #pragma unroll
      for (int w=0;w<4;w++) acc[u][v][w]=0.f;

  const int r = tid>>3, c4 = (tid&7)*4;
  for (int kb=0; kb<HID; kb+=32) {
    #pragma unroll
    for (int rr=r; rr<128; rr+=32) {
      float4 v = *reinterpret_cast<const float4*>(&x[(size_t)(m0+rr)*HID + kb + c4]);
      a_s[rr][c4]=f2tf(v.x); a_s[rr][c4+1]=f2tf(v.y);
      a_s[rr][c4+2]=f2tf(v.z); a_s[rr][c4+3]=f2tf(v.w);
    }
    #pragma unroll
    for (int rr=r; rr<128; rr+=32) {
      int j = (n0 + rr) & 1023;
      float4 v = *reinterpret_cast<const float4*>(&Wp[(size_t)j*2048 + kb + c4]);
      b_s[rr][c4]=f2tf(v.x); b_s[rr][c4+1]=f2tf(v.y);
      b_s[rr][c4+2]=f2tf(v.z); b_s[rr][c4+3]=f2tf(v.w);
    }
    __syncthreads();
    #pragma unroll
    for (int k8=0;k8<4;k8++){
      unsigned af[2][4], bfr[8][2];
      #pragma unroll
      for (int mt=0;mt<2;mt++){
        int row = wm*32 + mt*16;
        af[mt][0]=a_s[row+gid  ][k8*8+tig];
        af[mt][1]=a_s[row+gid+8][k8*8+tig];
        af[mt][2]=a_s[row+gid  ][k8*8+tig+4];
        af[mt][3]=a_s[row+gid+8][k8*8+tig+4];
      }
      #pragma unroll
      for (int nt=0;nt<8;nt++){
        int col = wn*64 + nt*8 + gid;
        bfr[nt][0]=b_s[col][k8*8+tig];
        bfr[nt][1]=b_s[col][k8*8+tig+4];
      }
      #pragma unroll
      for (int mt=0;mt<2;mt++)
        #pragma unroll
        for (int nt=0;nt<8;nt++)
          mma8(acc[mt][nt], af[mt], bfr[nt][0], bfr[nt][1]);
    }
    __syncthreads();
  }
  #pragma unroll
  for (int mt=0;mt<2;mt++){
    #pragma unroll
    for (int nt=0;nt<8;nt++){
      int row0 = m0 + wm*32 + mt*16 + gid;
      int col  = n0 + wn*64 + nt*8 + tig*2;
      int j = col & 1023;
      float b0v = bp[j], b1v = bp[j+1];
      int s0 = row0>>6,     bb0 = row0&63;
      int s1 = (row0+8)>>6, bb1 = (row0+8)&63;
      size_t base0 = (size_t)s0*((size_t)G4*BATCH) + (size_t)col*BATCH;
      size_t base1 = (size_t)s1*((size_t)G4*BATCH) + (size_t)col*BATCH;
      g_xz[base0 + bb0]         = acc[mt][nt][0] + b0v;
      g_xz[base0 + BATCH + bb0] = acc[mt][nt][1] + b1v;
      g_xz[base1 + bb1]         = acc[mt][nt][2] + b0v;
      g_xz[base1 + BATCH + bb1] = acc[mt][nt][3] + b1v;
    }
  }
}

// ---------------- phase 2 smem layout (byte offsets) -------------------------
#define OFF_WHV   0                      // 32 x 1024 u32 pre-arranged A-frags (131072 B)
#define OFF_HB0   131072                 // chunk buffer 0: 128 x 64 u32 (32768 B)
#define OFF_HB1   163840                 // chunk buffer 1
#define OFF_ZBUF  196608                 // 32 x 65 f32 (8320 B)
#define OFF_ZH    204928                 // 8 x 65 f32  (2080 B)
#define OFF_CS    207008                 // 64 x 8 f32  (2048 B)
#define OFF_MBAR  209056                 // 2 x 8 B
#define SMEM2_BYTES 209088

// ---------------- phase 2: persistent recurrent kernel -----------------------
// 128 CTAs (1/SM). CTA c owns hidden units j in [8c,8c+8): z^T[32 gate-j][64 b].
// A = Wh (smem, pre-arranged frags, LDS.128), B = h (bulk-copied 32KB k-chunks,
// swizzled [k][b]), 8 warps = 2 m-halves x 4 n-quarters, K=1024 streamed.
__global__ void __launch_bounds__(256,1) lstm_steps_kernel(
    const float* __restrict__ x, const float* __restrict__ c0,
    const float* __restrict__ Wf,const float* __restrict__ Wi,
    const float* __restrict__ Wg,const float* __restrict__ Wo,
    float* __restrict__ out)
{
  extern __shared__ char smem[];
  uint4*    whv  = reinterpret_cast<uint4*>(smem + OFF_WHV);
  unsigned* whvw = reinterpret_cast<unsigned*>(smem + OFF_WHV);
  unsigned* hb[2] = { reinterpret_cast<unsigned*>(smem + OFF_HB0),
                      reinterpret_cast<unsigned*>(smem + OFF_HB1) };
  float*    zbuf = reinterpret_cast<float*>(smem + OFF_ZBUF);   // stride 65
  float*    zh   = reinterpret_cast<float*>(smem + OFF_ZH);     // stride 65
  float*    cs   = reinterpret_cast<float*>(smem + OFF_CS);
  unsigned  mb_base = (unsigned)__cvta_generic_to_shared(smem + OFF_MBAR);
  unsigned  hb_sm[2] = { (unsigned)__cvta_generic_to_shared(smem + OFF_HB0),
                         (unsigned)__cvta_generic_to_shared(smem + OFF_HB1) };

  const int tid = threadIdx.x, wid = tid>>5, lane = tid&31;
  const int gid = lane>>2, tig = lane&3;
  const int mh = wid&1, nq = wid>>1;      // m-half (16 of 32), n-quarter (16 of 64)
  const int cta = blockIdx.x, j0 = cta*8;

  // ---- prologue: fill pre-arranged Wh frags -------------------------------
  // A-frag for (mh,k8,lane): e0=A[mh16+gid][8k8+tig] e1=A[+8][tig] e2=A[gid][tig+4] e3=A[+8][tig+4]
  for (int c = 0; c < 32; c++){
    int gatec = c & 3, jl = c >> 2;
    const float* Wp = (gatec==0)?Wf:(gatec==1)?Wi:(gatec==2)?Wg:Wo;
    float4 v = *reinterpret_cast<const float4*>(&Wp[(size_t)(j0+jl)*2048 + 1024 + tid*4]);
    int cmh = c>>4, cgid = c&7, ihalf = (c>>3)&1;
    float vv[4] = {v.x, v.y, v.z, v.w};
    #pragma unroll
    for (int q=0;q<4;q++){
      int k = tid*4 + q;
      int k8 = k>>3, ktig = k&3, khalf = (k>>2)&1;
      int e = ihalf + (khalf<<1);
      whvw[(((cmh*128 + k8)*32) + (cgid*4 + ktig))*4 + e] = f2tf(vv[q]);
    }
  }
  for (int t = tid; t < 512; t += 256) {
    int b = t>>3, jl = t&7;
    cs[t] = c0[b*HID + j0 + jl];
  }
  if (tid == 0){ mbar_init(mb_base, 1); mbar_init(mb_base+8, 1); }
  __syncthreads();

  unsigned ph[2] = {0u, 0u};
  const size_t HSEQ = (size_t)S_LEN*BATCH*HID;

  // per-thread B-column constants (swizzle XOR folded into column index)
  const int bcol0 = nq*16 + gid;               // nt=0
  const int bcol1 = nq*16 + 8 + gid;           // nt=1
  const unsigned bx0 = (unsigned)bcol0 ^ (unsigned)(tig<<3) ^ (unsigned)(((bcol0>>5)&1)<<2);
  const unsigned bx1 = (unsigned)bcol1 ^ (unsigned)(tig<<3) ^ (unsigned)(((bcol1>>5)&1)<<2);

  // xz prefetch (for step 0) — 4 x LDG.64 into registers
  float2 px[4];
  {
    const size_t sbase = 0;
    #pragma unroll
    for (int i2=0;i2<4;i2++){
      int nt = i2>>1, ih = i2&1;
      int c = mh*16 + gid + ih*8;
      int bc = nq*16 + nt*8 + 2*tig;
      int gcol = (c&3)*HID + j0 + (c>>2);
      px[i2] = *reinterpret_cast<const float2*>(&g_xz[sbase + (size_t)gcol*BATCH + bc]);
    }
  }

  for (int s=0; s<S_LEN; s++){
    const unsigned* hr = g_hT[s&1];

    // issue chunk 0 (h for this step is ready: gemm-init or previous barrier)
    if (tid == 0){
      asm volatile("fence.proxy.async;" ::: "memory");
      mbar_expect_tx(mb_base, 32768u);
      bulk_g2s(hb_sm[0], hr, 32768u, mb_base);
    }

    // init accumulators from prefetched xz (bias already included)
    float acc[2][4];
    #pragma unroll
    for (int i2=0;i2<4;i2++){
      int nt = i2>>1, ih = i2&1;
      acc[nt][ih*2+0] = px[i2].x;   // wait: map below
      acc[nt][ih*2+1] = px[i2].y;
    }
    // fix mapping: acc[nt][0]=(i0,c0) [nt][1]=(i0,c1) [nt][2]=(i1,c0) [nt][3]=(i1,c1)
    // px[i2]: nt=i2>>1, ih=i2&1 -> acc[nt][ih*2+e] matches (ih,e) ordering. OK.

    // prefetch xz for next step (independent of recurrence)
    if (s < S_LEN-1){
      const size_t sbase = (size_t)(s+1) * ((size_t)G4*BATCH);
      #pragma unroll
      for (int i2=0;i2<4;i2++){
        int nt = i2>>1, ih = i2&1;
        int c = mh*16 + gid + ih*8;
        int bc = nq*16 + nt*8 + 2*tig;
        int gcol = (c&3)*HID + j0 + (c>>2);
        px[i2] = *reinterpret_cast<const float2*>(&g_xz[sbase + (size_t)gcol*BATCH + bc]);
      }
    }

    // ---- K loop: 8 chunks of 128, double-buffered bulk copies --------------
    #pragma unroll 1
    for (int ch=0; ch<8; ch++){
      const int buf = ch&1;
      __syncthreads();                    // next buffer free (readers of ch-1 done)
      if (ch < 7 && tid == 0){
        mbar_expect_tx(mb_base + 8*(buf^1), 32768u);
        bulk_g2s(hb_sm[buf^1], hr + (ch+1)*128*64, 32768u, mb_base + 8*(buf^1));
      }
      mbar_wait(mb_base + 8*buf, ph[buf]);
      ph[buf] ^= 1u;

      const unsigned* hbp = hb[buf];
      #pragma unroll
      for (int k8l=0;k8l<16;k8l++){
        int kk = ch*16 + k8l;
        uint4 av = whv[(mh*128 + kk)*32 + lane];
        unsigned off0 = (unsigned)((k8l*8 + tig)*64);
        unsigned b00 = hbp[off0 + bx0];
        unsigned b01 = hbp[off0 + 256 + bx0];
        unsigned b10 = hbp[off0 + bx1];
        unsigned b11 = hbp[off0 + 256 + bx1];
        mma8(acc[0], reinterpret_cast<unsigned*>(&av), b00, b01);
        mma8(acc[1], reinterpret_cast<unsigned*>(&av), b10, b11);
      }
    }

    // ---- epilogue: z -> gates -> c,h --------------------------------------
    // stage z fragments: zbuf[c][b], stride 65
    #pragma unroll
    for (int nt=0;nt<2;nt++){
      int bc = nq*16 + nt*8 + 2*tig;
      int cA = mh*16 + gid, cB = cA + 8;
      zbuf[cA*65 + bc]   = acc[nt][0];
      zbuf[cA*65 + bc+1] = acc[nt][1];
      zbuf[cB*65 + bc]   = acc[nt][2];
      zbuf[cB*65 + bc+1] = acc[nt][3];
    }
    __syncthreads();

    unsigned* hwv = g_hT[(s+1)&1];
    #pragma unroll
    for (int p=0;p<2;p++){
      int jl = tid & 7;
      int b  = (tid >> 3) + p*32;
      int cbase = jl*4;
      float zf = zbuf[(cbase+0)*65 + b];
      float zi = zbuf[(cbase+1)*65 + b];
      float zg = zbuf[(cbase+2)*65 + b];
      float zo = zbuf[(cbase+3)*65 + b];
      float fg = 1.f/(1.f+__expf(-zf));
      float ig = 1.f/(1.f+__expf(-zi));
      float gg = tanhf(zg);
      float og = 1.f/(1.f+__expf(-zo));
      float cc = fg*cs[b*8+jl] + ig*gg;
      float hh = og*tanhf(cc);
      cs[b*8+jl] = cc;
      int j = j0 + jl;
      size_t xi = ((size_t)(s*BATCH + b))*HID + j;
      out[xi] = x[xi] + hh;
      zh[jl*65 + b] = hh;
      if (s == S_LEN-1){
        out[HSEQ + (size_t)b*HID + j]                     = hh;   // h_f
        out[HSEQ + (size_t)BATCH*HID + (size_t)b*HID + j] = cc;   // c_f
      }
    }
    __syncthreads();

    // h write: [k=j][b], swizzled, coalesced (warp = fixed j, 32 consecutive b)
    #pragma unroll
    for (int p=0;p<2;p++){
      int jl = tid >> 5;
      int b  = (tid & 31) + p*32;
      hwv[hswz(j0+jl, b)] = f2tf(zh[jl*65 + b]);
    }

    // grid barrier (skip after last step)
    if (s < S_LEN-1){
      __syncthreads();
      if (tid == 0){
        __threadfence();
        atomicAdd(&g_bar, 1u);
        unsigned target = (unsigned)RGRID * (unsigned)(s+1);
        while (ld_acq(&g_bar) < target) { }
      }
      __syncthreads();
    }
  }
}

// ---------------- launch ------------------------------------------------------
extern "C" void kernel_launch(void* const* d_in, const int* in_sizes, int n_in,
                              void* d_out, int out_size) {
  const float* x   = (const float*)d_in[0];
  const float* h0  = (const float*)d_in[1];
  const float* c0  = (const float*)d_in[2];
  const float* Wf  = (const float*)d_in[3];
  const float* bf_ = (const float*)d_in[4];
  const float* Wi  = (const float*)d_in[5];
  const float* bi_ = (const float*)d_in[6];
  const float* Wg  = (const float*)d_in[7];
  const float* bg_ = (const float*)d_in[8];
  const float* Wo  = (const float*)d_in[9];
  const float* bo_ = (const float*)d_in[10];
  float* out = (float*)d_out;

  cudaFuncSetAttribute(lstm_steps_kernel,
                       cudaFuncAttributeMaxDynamicSharedMemorySize, SMEM2_BYTES);

  gemm_xz_kernel<<<dim3(32,128),256>>>(x, h0, Wf,Wi,Wg,Wo, bf_,bi_,bg_,bo_);
  lstm_steps_kernel<<<RGRID,256,SMEM2_BYTES>>>(x, c0, Wf,Wi,Wg,Wo, out);
}